// round 7
// baseline (speedup 1.0000x reference)
#include <cuda_runtime.h>
#include <math.h>

#define B_ 8
#define H_ 128
#define W_ 128
#define G_ 64
#define C_ 20
#define GRID_ (B_ * H_)
#define PADR_ 21

__device__ double   d_partial[GRID_][6];
__device__ int      d_nv[B_];
__device__ unsigned d_ticket;   // zero-init; self-resets via atomicInc wrap

__global__ __launch_bounds__(256, 6) void fused_kernel(const float* __restrict__ kpt,
                                                       const float* __restrict__ preg,
                                                       const float* __restrict__ fpn,
                                                       const float* __restrict__ masks,
                                                       const float* __restrict__ gt,
                                                       const float* __restrict__ sy,
                                                       const float* __restrict__ sx,
                                                       float* __restrict__ out) {
    int tid = threadIdx.x;
    int x = tid & 127, s = tid >> 7;
    int bid = blockIdx.x, b = bid >> 7, y = bid & 127;

    __shared__ float4   sbox[G_];
    __shared__ float    ssfx[G_], sisx[G_], seyarg[G_], scyv[G_];
    __shared__ int      sseg[G_], sActG[G_];
    __shared__ unsigned skp[W_];
    __shared__ int      srg[W_ * PADR_];          // per-pixel per-class gaussian max (float bits)
    __shared__ float    sAmin[2][W_], sMl[2][W_], sMr[2][W_], sMt[2][W_], sMd[2][W_];
    __shared__ float    sLocA[2][W_], sIred[2][W_];
    __shared__ unsigned sHgb[2][W_];
    __shared__ float    sloc[W_];
    __shared__ unsigned shgb[W_];
    __shared__ int      s_nAct, s_nv, s_last;
    __shared__ float    scand[2];
    __shared__ int      scandi[2];
    __shared__ double   sacc[6][8];

    float yg = y + 0.5f, xg = x + 0.5f;

    // ---- init ----
    for (int i = tid; i < W_ * PADR_; i += 256) srg[i] = 0;
    if (tid < W_) skp[tid] = 0u;
    if (tid == 0) s_nAct = 0;

    // ---- per-gt constants (threads 0..63) ----
    float cyv = 0.f; int kyr = -1, kxr = 0;
    if (tid < G_) {
        const float* g7 = gt + (size_t)(b * G_ + tid) * 7;
        float cy = g7[0], cx = g7[1];
        cyv = cy; scyv[tid] = cy;
        sbox[tid] = make_float4((g7[3] + 0.5f) * 0.25f,   // bx1
                                (g7[5] + 0.5f) * 0.25f,   // bx2
                                (g7[2] + 0.5f) * 0.25f,   // by1
                                (g7[4] + 0.5f) * 0.25f);  // by2
        ssfx[tid] = floorf((cx + 0.5f) * 0.25f);
        float dy = (float)y - floorf((cy + 0.5f) * 0.25f);
        seyarg[tid] = -dy * dy * (0.5f / sy[b * G_ + tid]);
        sisx[tid]   = 0.5f / sx[b * G_ + tid];
        int cid = (int)g7[6] - 1;
        sseg[tid] = (cid >= 0 && cid < C_) ? cid : C_;
        kyr = min(max((int)floorf(cy * 0.25f), 0), H_ - 1);
        kxr = min(max((int)floorf(cx * 0.25f), 0), W_ - 1);
    }
    __syncthreads();

    // ---- parallel first-occurrence argmin over 64 gts ----
    if (tid < G_) {
        float v = cyv; int idx = tid;
#pragma unroll
        for (int off = 16; off; off >>= 1) {
            float ov = __shfl_down_sync(0xffffffffu, v, off);
            int   oi = __shfl_down_sync(0xffffffffu, idx, off);
            if (ov < v || (ov == v && oi < idx)) { v = ov; idx = oi; }
        }
        if ((tid & 31) == 0) { scand[tid >> 5] = v; scandi[tid >> 5] = idx; }
    }
    __syncthreads();
    if (tid == 0) {
        float v0 = scand[0], v1 = scand[1];
        int   i0 = scandi[0], i1 = scandi[1];
        int am = (v1 < v0 || (v1 == v0 && i1 < i0)) ? i1 : i0;
        s_nv = am;
        if (y == 0) d_nv[b] = am;
    }
    __syncthreads();
    int nv = s_nv;

    // ---- row compaction + kp scatter ----
    if (tid < nv) {
        float4 bb = sbox[tid];
        float t = yg - bb.z, dd = bb.w - yg;
        if (t > 0.f && dd > 0.f) {
            int a = atomicAdd(&s_nAct, 1);
            sActG[a] = tid | (sseg[tid] << 8);
        }
        if (sseg[tid] < C_ && kyr == y)
            atomicOr(&skp[kxr], 1u << sseg[tid]);
    }
    __syncthreads();
    int nA = s_nAct;
    size_t rowoff = (size_t)bid * W_;

    // ---- geometry: slice s handles entries a = s, s+2, ... ----
    {
        const float* mrow = masks + (rowoff + x) * G_;
        float area_min = 1e8f, loc = 0.f;
        float ml = 0.f, mr = 0.f, mt = 0.f, md = 0.f;
        unsigned hgb = 0u;
        for (int a = s; a < nA; a += 2) {
            int pk = sActG[a];
            int g = pk & 255, cg = pk >> 8;
            float4 bb = sbox[g];
            float l = xg - bb.x, r = bb.y - xg, t = yg - bb.z, d = bb.w - yg;
            float m = __ldg(&mrow[g]);
            float hm = (l > 0.f && r > 0.f) ? m : 0.f;
            loc = fmaxf(loc, hm);
            float lh = l * hm, rh = r * hm, th = t * hm, dh = d * hm;
            float ap = (lh + rh) * (th + dh) + (1.f - hm) * 1e8f;
            if (ap < area_min) {
                area_min = ap; ml = lh; mr = rh; mt = th; md = dh; hgb = 1u << cg;
            } else if (ap == area_min) {
                ml = fmaxf(ml, lh); mr = fmaxf(mr, rh);
                mt = fmaxf(mt, th); md = fmaxf(md, dh);
                hgb |= 1u << cg;
            }
        }
        sAmin[s][x] = area_min;
        sMl[s][x] = ml; sMr[s][x] = mr; sMt[s][x] = mt; sMd[s][x] = md;
        sLocA[s][x] = loc; sHgb[s][x] = hgb;
    }

    // ---- gaussian: slice s handles g = s, s+2, ...  (atomic scatter-max) ----
    {
        float ired = 0.f, xf = (float)x;
        for (int g = s; g < nv; g += 2) {
            float dxx = xf - ssfx[g];
            float red = __expf(fmaf(-dxx * dxx, sisx[g], seyarg[g]));
            ired = fmaxf(ired, red);
            int c = sseg[g];
            if (c < C_) atomicMax(&srg[x * PADR_ + c], __float_as_int(red));
        }
        sIred[s][x] = ired;
    }
    __syncthreads();

    // ---- merge + IoU term (slice 0 only) ----
    float iou_t = 0.f, locv = 0.f;
    if (s == 0) {
        float am0 = sAmin[0][x], am1 = sAmin[1][x];
        float Ml, Mr, Mt, Md; unsigned hb;
        if (am0 < am1)      { Ml = sMl[0][x]; Mr = sMr[0][x]; Mt = sMt[0][x]; Md = sMd[0][x]; hb = sHgb[0][x]; }
        else if (am1 < am0) { Ml = sMl[1][x]; Mr = sMr[1][x]; Mt = sMt[1][x]; Md = sMd[1][x]; hb = sHgb[1][x]; }
        else {
            Ml = fmaxf(sMl[0][x], sMl[1][x]); Mr = fmaxf(sMr[0][x], sMr[1][x]);
            Mt = fmaxf(sMt[0][x], sMt[1][x]); Md = fmaxf(sMd[0][x], sMd[1][x]);
            hb = sHgb[0][x] | sHgb[1][x];
        }
        locv = fmaxf(sLocA[0][x], sLocA[1][x]);
        if (locv == 0.f) hb = 0u;
        sloc[x] = locv; shgb[x] = hb;
        float dl = Ml * locv, dr = Mr * locv, dt = Mt * locv, db = Md * locv;
        float ired = fmaxf(sIred[0][x], sIred[1][x]);
        float4 pv = reinterpret_cast<const float4*>(preg)[rowoff + x];
        float inter = (fminf(dl, pv.x) + fminf(dr, pv.y)) * (fminf(dt, pv.z) + fminf(db, pv.w));
        float uni   = (dl + dr) * (dt + db) + (pv.x + pv.y) * (pv.z + pv.w) - inter;
        iou_t = -__logf(inter / (uni + 1e-12f) + 1e-12f) * locv * (ired * 4.f + 1.f);
    }
    __syncthreads();

    // ---- focal losses: all 256 threads, flat coalesced loop ----
    float grav = 0.f, hpos = 0.f, hneg = 0.f, shg = 0.f;
    const float4* kr4 = reinterpret_cast<const float4*>(kpt + rowoff * C_);
    const float4* fr4 = reinterpret_cast<const float4*>(fpn + rowoff * C_);
#pragma unroll
    for (int ch = 0; ch < 3; ch++) {
        int i4 = ch * 256 + tid;
        if (i4 < W_ * C_ / 4) {
            float4 kv = __ldg(&kr4[i4]);
            float4 fv = __ldg(&fr4[i4]);
            float ka[4] = { kv.x, kv.y, kv.z, kv.w };
            float fa[4] = { fv.x, fv.y, fv.z, fv.w };
#pragma unroll
            for (int e = 0; e < 4; e++) {
                int i = i4 * 4 + e;
                int xx = i / C_, cc = i - xx * C_;
                float rg = __int_as_float(srg[xx * PADR_ + cc]);
                float hg = ((shgb[xx] >> cc) & 1u) ? sloc[xx] : 0.f;
                float p  = fminf(fmaxf(ka[e], -30.f), 30.f);
                float e1 = __expf(-p);
                float L1 = __logf(1.f + e1);
                float iv = __fdividef(1.f, 1.f + e1);
                float om = e1 * iv;
                float q  = 1.f - rg; q = q * q; q = q * q;
                grav += ((skp[xx] >> cc) & 1u) ? (om * om * L1)
                                               : (q * iv * iv * (p + L1));
                float f   = fminf(fmaxf(fa[e], -30.f), 30.f);
                float e2  = __expf(-f);
                float L2  = __logf(1.f + e2);
                float iv2 = __fdividef(1.f, 1.f + e2);
                float om2 = e2 * iv2;
                hpos += om2 * om2 * L2 * hg;
                hneg += iv2 * iv2 * (f + L2);
                shg  += hg;
            }
        }
    }

    // ---- deterministic block reduction (8 warps) ----
    float v[6] = { iou_t, locv, grav, hpos * 10.f, hneg * 10.f, shg };
#pragma unroll
    for (int off = 16; off; off >>= 1)
#pragma unroll
        for (int k = 0; k < 6; k++) v[k] += __shfl_down_sync(0xffffffffu, v[k], off);
    int w = tid >> 5, lane = tid & 31;
    __syncthreads();
    if (lane == 0)
#pragma unroll
        for (int k = 0; k < 6; k++) sacc[k][w] = (double)v[k];
    __syncthreads();
    if (tid == 0) {
#pragma unroll
        for (int k = 0; k < 6; k++) {
            double t0 = sacc[k][0] + sacc[k][1] + sacc[k][2] + sacc[k][3];
            double t1 = sacc[k][4] + sacc[k][5] + sacc[k][6] + sacc[k][7];
            d_partial[bid][k] = t0 + t1;
        }
        __threadfence();
        unsigned old = atomicInc(&d_ticket, GRID_ - 1);   // wraps -> self-reset
        s_last = (old == GRID_ - 1);
    }
    __syncthreads();

    // ---- last block: deterministic final combine ----
    if (s_last) {
        __threadfence();
        int t = tid;
        double tot = 0.0;
        for (int bb = 0; bb < B_; bb++) {
            double u[6];
#pragma unroll
            for (int k = 0; k < 6; k++) u[k] = (t < 128) ? d_partial[bb * H_ + t][k] : 0.0;
#pragma unroll
            for (int off = 16; off; off >>= 1)
#pragma unroll
                for (int k = 0; k < 6; k++) u[k] += __shfl_down_sync(0xffffffffu, u[k], off);
            __syncthreads();
            if ((t & 31) == 0)
#pragma unroll
                for (int k = 0; k < 6; k++) sacc[k][t >> 5] = u[k];
            __syncthreads();
            if (t == 0) {
                double iouS  = sacc[0][0] + sacc[0][1] + sacc[0][2] + sacc[0][3];
                double slocS = sacc[1][0] + sacc[1][1] + sacc[1][2] + sacc[1][3];
                double gravS = sacc[2][0] + sacc[2][1] + sacc[2][2] + sacc[2][3];
                double hposS = sacc[3][0] + sacc[3][1] + sacc[3][2] + sacc[3][3];
                double hnegS = sacc[4][0] + sacc[4][1] + sacc[4][2] + sacc[4][3];
                double shgS  = sacc[5][0] + sacc[5][1] + sacc[5][2] + sacc[5][3];
                double HWC = (double)(H_ * W_ * C_);
                double hm_loss = hnegS / (HWC - shgS);
                bool cond = (shgS != 0.0);
                double hm2 = hm_loss + hposS / (cond ? shgS : 1.0);
                double safe_loc = (slocS > 0.0) ? slocS : 1.0;
                double iou_out = cond ? (iouS / safe_loc) : 0.0;
                double nvf = (d_nv[bb] > 1) ? (double)d_nv[bb] : 1.0;
                double grav_out = cond ? (gravS / nvf) : 0.0;
                tot += cond ? (iou_out + grav_out + hm2) : hm_loss;
            }
        }
        if (t == 0) out[0] = (float)(tot * (1.0 / B_));
    }
}

// ---------------- launch ----------------
extern "C" void kernel_launch(void* const* d_in, const int* in_sizes, int n_in,
                              void* d_out, int out_size) {
    const float* keypoints = (const float*)d_in[0];
    const float* preg      = (const float*)d_in[1];
    const float* fpn       = (const float*)d_in[2];
    const float* gt        = (const float*)d_in[3];
    const float* masks     = (const float*)d_in[4];
    const float* sy        = (const float*)d_in[5];
    const float* sx        = (const float*)d_in[6];
    (void)in_sizes; (void)n_in; (void)out_size;

    fused_kernel<<<GRID_, 256>>>(keypoints, preg, fpn, masks, gt, sy, sx, (float*)d_out);
}

// round 8
// speedup vs baseline: 1.1158x; 1.1158x over previous
#include <cuda_runtime.h>
#include <math.h>

#define B_ 8
#define H_ 128
#define W_ 128
#define G_ 64
#define C_ 20
#define HW_ 64                     // pixels per block (half row)
#define GRID_ (B_ * H_ * 2)        // 2048 blocks
#define PADR_ 21

__device__ double   d_partial[GRID_][6];
__device__ int      d_nv[B_];
__device__ unsigned d_ticket;      // zero-init; self-resets via atomicInc wrap

__global__ __launch_bounds__(128) void fused_kernel(const float* __restrict__ kpt,
                                                    const float* __restrict__ preg,
                                                    const float* __restrict__ fpn,
                                                    const float* __restrict__ masks,
                                                    const float* __restrict__ gt,
                                                    const float* __restrict__ sy,
                                                    const float* __restrict__ sx,
                                                    float* __restrict__ out) {
    int tid = threadIdx.x;
    int bid = blockIdx.x;
    int hb = bid & 1, y = (bid >> 1) & 127, b = bid >> 8;
    int x0 = hb * HW_;

    __shared__ float4   sbox[G_];
    __shared__ float    ssfx[G_], sisx[G_], seyarg[G_];
    __shared__ int      sseg[G_], sActG[G_];
    __shared__ unsigned skp[HW_];
    __shared__ float    srg[HW_][PADR_];      // per-pixel per-class gaussian max
    __shared__ float    sIred[HW_];
    __shared__ float    sloc[HW_];
    __shared__ unsigned shgb[HW_];
    __shared__ int      s_nAct, s_nv, s_last;
    __shared__ float    scand[2];
    __shared__ int      scandi[2];
    __shared__ double   sacc[6][4];

    float yg = y + 0.5f;

    if (tid < HW_) skp[tid] = 0u;
    if (tid == 0) s_nAct = 0;

    // ---- per-gt constants (threads 0..63, one gt each) ----
    float cyv = 0.f; int kyr = -1, kxr = 0;
    if (tid < G_) {
        const float* g7 = gt + (size_t)(b * G_ + tid) * 7;
        float cy = g7[0], cx = g7[1];
        cyv = cy;
        sbox[tid] = make_float4((g7[3] + 0.5f) * 0.25f,   // bx1
                                (g7[5] + 0.5f) * 0.25f,   // bx2
                                (g7[2] + 0.5f) * 0.25f,   // by1
                                (g7[4] + 0.5f) * 0.25f);  // by2
        ssfx[tid] = floorf((cx + 0.5f) * 0.25f);
        float dy = (float)y - floorf((cy + 0.5f) * 0.25f);
        seyarg[tid] = -dy * dy * (0.5f / sy[b * G_ + tid]);
        sisx[tid]   = 0.5f / sx[b * G_ + tid];
        int cid = (int)g7[6] - 1;
        sseg[tid] = (cid >= 0 && cid < C_) ? cid : C_;
        kyr = min(max((int)floorf(cy * 0.25f), 0), H_ - 1);
        kxr = min(max((int)floorf(cx * 0.25f), 0), W_ - 1);
    }
    __syncthreads();

    // ---- parallel first-occurrence argmin over 64 gts ----
    if (tid < G_) {
        float v = cyv; int idx = tid;
#pragma unroll
        for (int off = 16; off; off >>= 1) {
            float ov = __shfl_down_sync(0xffffffffu, v, off);
            int   oi = __shfl_down_sync(0xffffffffu, idx, off);
            if (ov < v || (ov == v && oi < idx)) { v = ov; idx = oi; }
        }
        if ((tid & 31) == 0) { scand[tid >> 5] = v; scandi[tid >> 5] = idx; }
    }
    __syncthreads();
    if (tid == 0) {
        float v0 = scand[0], v1 = scand[1];
        int   i0 = scandi[0], i1 = scandi[1];
        int am = (v1 < v0 || (v1 == v0 && i1 < i0)) ? i1 : i0;
        s_nv = am;
        if (y == 0 && hb == 0) d_nv[b] = am;
    }
    __syncthreads();
    int nv = s_nv;

    // ---- row compaction + kp scatter (threads 0..nv-1) ----
    if (tid < nv) {
        float4 bb = sbox[tid];
        float t = yg - bb.z, dd = bb.w - yg;
        if (t > 0.f && dd > 0.f) {
            int a = atomicAdd(&s_nAct, 1);
            sActG[a] = tid | (sseg[tid] << 8);
        }
        if (sseg[tid] < C_ && kyr == y && (kxr >> 6) == hb)
            atomicOr(&skp[kxr & 63], 1u << sseg[tid]);
    }
    __syncthreads();
    int nA = s_nAct;
    size_t rowoff = (size_t)(b * H_ + y) * W_;

    // ====== disjoint phases: lower half = geometry, upper half = gaussian ======
    float dl = 0.f, dr = 0.f, dt = 0.f, db = 0.f, locv = 0.f;
    if (tid < HW_) {
        // ---- geometry for pixel x0+tid ----
        int xp = x0 + tid;
        float xg = xp + 0.5f;
        const float* mrow = masks + (rowoff + xp) * G_;
        float area_min = 1e8f, loc = 0.f;
        float ml = 0.f, mr = 0.f, mt = 0.f, md = 0.f;
        unsigned hgb = 0u;
        for (int a = 0; a < nA; a++) {
            int pk = sActG[a];
            int g = pk & 255, cg = pk >> 8;
            float4 bb = sbox[g];
            float l = xg - bb.x, r = bb.y - xg, t = yg - bb.z, d = bb.w - yg;
            float m = __ldg(&mrow[g]);
            float hm = (l > 0.f && r > 0.f) ? m : 0.f;
            loc = fmaxf(loc, hm);
            float lh = l * hm, rh = r * hm, th = t * hm, dh = d * hm;
            float ap = (lh + rh) * (th + dh) + (1.f - hm) * 1e8f;
            if (ap < area_min) {
                area_min = ap; ml = lh; mr = rh; mt = th; md = dh; hgb = 1u << cg;
            } else if (ap == area_min) {
                ml = fmaxf(ml, lh); mr = fmaxf(mr, rh);
                mt = fmaxf(mt, th); md = fmaxf(md, dh);
                hgb |= 1u << cg;
            }
        }
        if (loc == 0.f) hgb = 0u;
        locv = loc;
        dl = ml * loc; dr = mr * loc; dt = mt * loc; db = md * loc;
        sloc[tid] = loc;
        shgb[tid] = hgb;
    } else {
        // ---- gaussian scan for pixel x0 + (tid-64) ----
        int px = tid - HW_;
        float xf = (float)(x0 + px);
        float* rg = srg[px];
#pragma unroll
        for (int c = 0; c < C_; c++) rg[c] = 0.f;
        float ired = 0.f;
        for (int g = 0; g < nv; g++) {
            float dxx = xf - ssfx[g];
            float red = __expf(fmaf(-dxx * dxx, sisx[g], seyarg[g]));
            ired = fmaxf(ired, red);
            int c = sseg[g];
            if (c < C_) rg[c] = fmaxf(rg[c], red);
        }
        sIred[px] = ired;
    }
    __syncthreads();

    // ---- IoU term (threads 0..63) ----
    float iou_t = 0.f;
    if (tid < HW_) {
        float4 pv = reinterpret_cast<const float4*>(preg)[rowoff + x0 + tid];
        float inter = (fminf(dl, pv.x) + fminf(dr, pv.y)) * (fminf(dt, pv.z) + fminf(db, pv.w));
        float uni   = (dl + dr) * (dt + db) + (pv.x + pv.y) * (pv.z + pv.w) - inter;
        iou_t = -__logf(inter / (uni + 1e-12f) + 1e-12f) * locv * (sIred[tid] * 4.f + 1.f);
    }

    // ---- focal losses: all 128 threads over HW_*C_ = 1280 elements ----
    float grav = 0.f, hpos = 0.f, hneg = 0.f, shg = 0.f;
    const float4* kr4 = reinterpret_cast<const float4*>(kpt + (rowoff + x0) * C_);
    const float4* fr4 = reinterpret_cast<const float4*>(fpn + (rowoff + x0) * C_);
#pragma unroll
    for (int ch = 0; ch < 3; ch++) {
        int i4 = ch * 128 + tid;
        if (i4 < HW_ * C_ / 4) {
            float4 kv = __ldg(&kr4[i4]);
            float4 fv = __ldg(&fr4[i4]);
            float ka[4] = { kv.x, kv.y, kv.z, kv.w };
            float fa[4] = { fv.x, fv.y, fv.z, fv.w };
#pragma unroll
            for (int e = 0; e < 4; e++) {
                int i = i4 * 4 + e;
                int xx = i / C_, cc = i - xx * C_;
                float rg = srg[xx][cc];
                float hg = ((shgb[xx] >> cc) & 1u) ? sloc[xx] : 0.f;
                float p  = fminf(fmaxf(ka[e], -30.f), 30.f);
                float e1 = __expf(-p);
                float L1 = __logf(1.f + e1);
                float iv = __fdividef(1.f, 1.f + e1);
                float om = e1 * iv;
                float q  = 1.f - rg; q = q * q; q = q * q;
                grav += ((skp[xx] >> cc) & 1u) ? (om * om * L1)
                                               : (q * iv * iv * (p + L1));
                float f   = fminf(fmaxf(fa[e], -30.f), 30.f);
                float e2  = __expf(-f);
                float L2  = __logf(1.f + e2);
                float iv2 = __fdividef(1.f, 1.f + e2);
                float om2 = e2 * iv2;
                hpos += om2 * om2 * L2 * hg;
                hneg += iv2 * iv2 * (f + L2);
                shg  += hg;
            }
        }
    }

    // ---- deterministic block reduction (4 warps) ----
    float v[6] = { iou_t, locv, grav, hpos * 10.f, hneg * 10.f, shg };
#pragma unroll
    for (int off = 16; off; off >>= 1)
#pragma unroll
        for (int k = 0; k < 6; k++) v[k] += __shfl_down_sync(0xffffffffu, v[k], off);
    int w = tid >> 5, lane = tid & 31;
    __syncthreads();
    if (lane == 0)
#pragma unroll
        for (int k = 0; k < 6; k++) sacc[k][w] = (double)v[k];
    __syncthreads();
    if (tid == 0) {
#pragma unroll
        for (int k = 0; k < 6; k++)
            d_partial[bid][k] = sacc[k][0] + sacc[k][1] + sacc[k][2] + sacc[k][3];
        __threadfence();
        unsigned old = atomicInc(&d_ticket, GRID_ - 1);   // wraps -> self-reset
        s_last = (old == GRID_ - 1);
    }
    __syncthreads();

    // ---- last block: deterministic final combine (256 rows per image) ----
    if (s_last) {
        __threadfence();
        int t = tid;
        double tot = 0.0;
        for (int bb = 0; bb < B_; bb++) {
            double u[6];
#pragma unroll
            for (int k = 0; k < 6; k++)
                u[k] = d_partial[bb * 256 + t][k] + d_partial[bb * 256 + 128 + t][k];
#pragma unroll
            for (int off = 16; off; off >>= 1)
#pragma unroll
                for (int k = 0; k < 6; k++) u[k] += __shfl_down_sync(0xffffffffu, u[k], off);
            __syncthreads();
            if ((t & 31) == 0)
#pragma unroll
                for (int k = 0; k < 6; k++) sacc[k][t >> 5] = u[k];
            __syncthreads();
            if (t == 0) {
                double iouS  = sacc[0][0] + sacc[0][1] + sacc[0][2] + sacc[0][3];
                double slocS = sacc[1][0] + sacc[1][1] + sacc[1][2] + sacc[1][3];
                double gravS = sacc[2][0] + sacc[2][1] + sacc[2][2] + sacc[2][3];
                double hposS = sacc[3][0] + sacc[3][1] + sacc[3][2] + sacc[3][3];
                double hnegS = sacc[4][0] + sacc[4][1] + sacc[4][2] + sacc[4][3];
                double shgS  = sacc[5][0] + sacc[5][1] + sacc[5][2] + sacc[5][3];
                double HWC = (double)(H_ * W_ * C_);
                double hm_loss = hnegS / (HWC - shgS);
                bool cond = (shgS != 0.0);
                double hm2 = hm_loss + hposS / (cond ? shgS : 1.0);
                double safe_loc = (slocS > 0.0) ? slocS : 1.0;
                double iou_out = cond ? (iouS / safe_loc) : 0.0;
                double nvf = (d_nv[bb] > 1) ? (double)d_nv[bb] : 1.0;
                double grav_out = cond ? (gravS / nvf) : 0.0;
                tot += cond ? (iou_out + grav_out + hm2) : hm_loss;
            }
        }
        if (t == 0) out[0] = (float)(tot * (1.0 / B_));
    }
}

// ---------------- launch ----------------
extern "C" void kernel_launch(void* const* d_in, const int* in_sizes, int n_in,
                              void* d_out, int out_size) {
    const float* keypoints = (const float*)d_in[0];
    const float* preg      = (const float*)d_in[1];
    const float* fpn       = (const float*)d_in[2];
    const float* gt        = (const float*)d_in[3];
    const float* masks     = (const float*)d_in[4];
    const float* sy        = (const float*)d_in[5];
    const float* sx        = (const float*)d_in[6];
    (void)in_sizes; (void)n_in; (void)out_size;

    fused_kernel<<<GRID_, 128>>>(keypoints, preg, fpn, masks, gt, sy, sx, (float*)d_out);
}

// round 9
// speedup vs baseline: 1.8810x; 1.6857x over previous
#include <cuda_runtime.h>
#include <math.h>
#include <float.h>

#define B_ 8
#define H_ 128
#define W_ 128
#define G_ 64
#define C_ 20
#define PAD_ 22
#define GRID_ (B_ * H_)

__device__ double   d_partial[GRID_][6];
__device__ int      d_nv[B_];
__device__ unsigned d_ticket;   // zero-init; self-resets via atomicInc wrap

__global__ __launch_bounds__(128) void fused_kernel(const float* __restrict__ kpt,
                                                    const float* __restrict__ preg,
                                                    const float* __restrict__ fpn,
                                                    const float* __restrict__ masks,
                                                    const float* __restrict__ gt,
                                                    const float* __restrict__ sy,
                                                    const float* __restrict__ sx,
                                                    float* __restrict__ out) {
    int bid = blockIdx.x;
    int b = bid >> 7, y = bid & 127;
    int x = threadIdx.x;

    __shared__ float4   sbox[G_];
    __shared__ float    ssfx[G_], sisx[G_], seyarg[G_];
    __shared__ int      sseg[G_];
    __shared__ int      sActG[G_];            // packed g | seg<<8
    __shared__ unsigned skp[W_], shgb[W_];
    __shared__ float    sloc[W_];
    __shared__ float    srg[W_][PAD_];        // per-pixel per-class gaussian max
    __shared__ int      s_nAct, s_nv, s_last;
    __shared__ float    scand[2];
    __shared__ int      scandi[2];
    __shared__ double   sacc[6][4];

    float yg = y + 0.5f, xg = x + 0.5f;

    // ---- phase A: init + per-gt constants ----
    skp[x] = 0u;
#pragma unroll
    for (int c = 0; c < C_; c++) srg[x][c] = 0.f;

    int kyr = -1, kxr = 0;
    float cyv = 0.f;
    if (x < G_) {
        const float* g7 = gt + (size_t)(b * G_ + x) * 7;
        float cy = g7[0], cx = g7[1];
        cyv = cy;
        sbox[x] = make_float4((g7[3] + 0.5f) * 0.25f,   // bx1
                              (g7[5] + 0.5f) * 0.25f,   // bx2
                              (g7[2] + 0.5f) * 0.25f,   // by1
                              (g7[4] + 0.5f) * 0.25f);  // by2
        ssfx[x] = floorf((cx + 0.5f) * 0.25f);
        float dy = (float)y - floorf((cy + 0.5f) * 0.25f);
        seyarg[x] = -dy * dy * (0.5f / sy[b * G_ + x]);
        sisx[x]   = 0.5f / sx[b * G_ + x];
        int cid = (int)g7[6] - 1;
        sseg[x] = (cid >= 0 && cid < C_) ? cid : C_;
        kyr = min(max((int)floorf(cy * 0.25f), 0), H_ - 1);
        kxr = min(max((int)floorf(cx * 0.25f), 0), W_ - 1);
    }
    __syncthreads();

    // ---- parallel first-occurrence argmin over 64 gts ----
    if (x < G_) {
        float v = cyv; int idx = x;
#pragma unroll
        for (int off = 16; off; off >>= 1) {
            float ov = __shfl_down_sync(0xffffffffu, v, off);
            int   oi = __shfl_down_sync(0xffffffffu, idx, off);
            if (ov < v || (ov == v && oi < idx)) { v = ov; idx = oi; }
        }
        if ((x & 31) == 0) { scand[x >> 5] = v; scandi[x >> 5] = idx; }
    }
    __syncthreads();
    if (x == 0) {
        float v0 = scand[0], v1 = scand[1];
        int   i0 = scandi[0], i1 = scandi[1];
        int am = (v1 < v0 || (v1 == v0 && i1 < i0)) ? i1 : i0;
        s_nv = am;
        s_nAct = 0;
        if (y == 0) d_nv[b] = am;
    }
    __syncthreads();
    int nv = s_nv;

    // ---- compaction of row-active gts + kp scatter ----
    if (x < nv) {
        float4 bb = sbox[x];
        float t = yg - bb.z, dd = bb.w - yg;
        if (t > 0.f && dd > 0.f) {
            int a = atomicAdd(&s_nAct, 1);
            sActG[a] = x | (sseg[x] << 8);
        }
        if (sseg[x] < C_ && kyr == y)
            atomicOr(&skp[kxr], 1u << sseg[x]);
    }
    __syncthreads();

    int nA = s_nAct;
    size_t rowoff = (size_t)bid * W_;

    // prefetch preg early (overlaps with geometry loop)
    float4 pv = __ldg(&reinterpret_cast<const float4*>(preg)[rowoff + x]);

    // ---- geometry: single pass, MLP-4 mask prefetch, exact tie-merging argmin ----
    const float* mrow = masks + (rowoff + x) * G_;
    float area_min = 1e8f, loc = 0.f;
    float ml = 0.f, mr = 0.f, mt = 0.f, mb = 0.f;
    unsigned hgb = 0u;
    int a = 0;
    for (; a + 4 <= nA; a += 4) {
        int pk0 = sActG[a], pk1 = sActG[a + 1], pk2 = sActG[a + 2], pk3 = sActG[a + 3];
        // issue 4 independent mask loads back-to-back (MLP=4)
        float m0 = __ldg(&mrow[pk0 & 255]);
        float m1 = __ldg(&mrow[pk1 & 255]);
        float m2 = __ldg(&mrow[pk2 & 255]);
        float m3 = __ldg(&mrow[pk3 & 255]);
        int   pks[4] = { pk0, pk1, pk2, pk3 };
        float ms[4]  = { m0, m1, m2, m3 };
#pragma unroll
        for (int e = 0; e < 4; e++) {
            int g = pks[e] & 255, cg = pks[e] >> 8;
            float4 bb = sbox[g];
            float l = xg - bb.x, r = bb.y - xg, t = yg - bb.z, d = bb.w - yg;
            float hm = (l > 0.f && r > 0.f) ? ms[e] : 0.f;
            loc = fmaxf(loc, hm);
            float lh = l * hm, rh = r * hm, th = t * hm, dh = d * hm;
            float ap = (lh + rh) * (th + dh) + (1.f - hm) * 1e8f;
            if (ap < area_min) {
                area_min = ap; ml = lh; mr = rh; mt = th; mb = dh; hgb = 1u << cg;
            } else if (ap == area_min) {
                ml = fmaxf(ml, lh); mr = fmaxf(mr, rh);
                mt = fmaxf(mt, th); mb = fmaxf(mb, dh);
                hgb |= 1u << cg;
            }
        }
    }
    for (; a < nA; a++) {
        int pk = sActG[a];
        int g = pk & 255, cg = pk >> 8;
        float4 bb = sbox[g];
        float l = xg - bb.x, r = bb.y - xg, t = yg - bb.z, d = bb.w - yg;
        float m = __ldg(&mrow[g]);
        float hm = (l > 0.f && r > 0.f) ? m : 0.f;
        loc = fmaxf(loc, hm);
        float lh = l * hm, rh = r * hm, th = t * hm, dh = d * hm;
        float ap = (lh + rh) * (th + dh) + (1.f - hm) * 1e8f;
        if (ap < area_min) {
            area_min = ap; ml = lh; mr = rh; mt = th; mb = dh; hgb = 1u << cg;
        } else if (ap == area_min) {
            ml = fmaxf(ml, lh); mr = fmaxf(mr, rh);
            mt = fmaxf(mt, th); mb = fmaxf(mb, dh);
            hgb |= 1u << cg;
        }
    }
    if (loc == 0.f) hgb = 0u;
    float dl = ml * loc, dr = mr * loc, dt = mt * loc, db = mb * loc;

    // ---- gaussian scan: iou_red + per-class scatter-max into srg ----
    float iou_red = 0.f, xf = (float)x;
    for (int g = 0; g < nv; g++) {
        float dxx = xf - ssfx[g];
        float red = __expf(fmaf(-dxx * dxx, sisx[g], seyarg[g]));
        iou_red = fmaxf(iou_red, red);
        int c = sseg[g];
        if (c < C_) srg[x][c] = fmaxf(srg[x][c], red);
    }
    sloc[x] = loc;
    shgb[x] = hgb;
    __syncthreads();

    // ---- IoU term (thread = pixel x) ----
    float inter = (fminf(dl, pv.x) + fminf(dr, pv.y)) * (fminf(dt, pv.z) + fminf(db, pv.w));
    float uni   = (dl + dr) * (dt + db) + (pv.x + pv.y) * (pv.z + pv.w) - inter;
    float iou_t = -__logf(inter / (uni + 1e-12f) + 1e-12f) * loc * (iou_red * 4.f + 1.f);

    // ---- focal losses: flat coalesced loop over W*C elements ----
    float grav = 0.f, hpos = 0.f, hneg = 0.f, shg = 0.f;
    const float4* kr4 = reinterpret_cast<const float4*>(kpt + rowoff * C_);
    const float4* fr4 = reinterpret_cast<const float4*>(fpn + rowoff * C_);
#pragma unroll
    for (int ch = 0; ch < (W_ * C_ / 4) / 128; ch++) {
        int i4 = ch * 128 + x;
        float4 kv = __ldg(&kr4[i4]);
        float4 fv = __ldg(&fr4[i4]);
        float ka[4] = { kv.x, kv.y, kv.z, kv.w };
        float fa[4] = { fv.x, fv.y, fv.z, fv.w };
#pragma unroll
        for (int e = 0; e < 4; e++) {
            int i = i4 * 4 + e;
            int xx = i / C_, cc = i - xx * C_;
            float rg = srg[xx][cc];
            float hg = ((shgb[xx] >> cc) & 1u) ? sloc[xx] : 0.f;
            // gravity focal
            float p  = fminf(fmaxf(ka[e], -30.f), 30.f);
            float e1 = __expf(-p);
            float L1 = __logf(1.f + e1);
            float iv = __fdividef(1.f, 1.f + e1);
            float om = e1 * iv;
            float q  = 1.f - rg; q = q * q; q = q * q;
            grav += ((skp[xx] >> cc) & 1u) ? (om * om * L1)
                                           : (q * iv * iv * (p + L1));
            // heatmap focal
            float f   = fminf(fmaxf(fa[e], -30.f), 30.f);
            float e2  = __expf(-f);
            float L2  = __logf(1.f + e2);
            float iv2 = __fdividef(1.f, 1.f + e2);
            float om2 = e2 * iv2;
            hpos += om2 * om2 * L2 * hg;
            hneg += iv2 * iv2 * (f + L2);
            shg  += hg;
        }
    }

    // ---- deterministic block reduction (float tree, double store) ----
    float v[6] = { iou_t, loc, grav, hpos * 10.f, hneg * 10.f, shg };
#pragma unroll
    for (int off = 16; off; off >>= 1)
#pragma unroll
        for (int k = 0; k < 6; k++) v[k] += __shfl_down_sync(0xffffffffu, v[k], off);
    int w = x >> 5, lane = x & 31;
    __syncthreads();
    if (lane == 0)
#pragma unroll
        for (int k = 0; k < 6; k++) sacc[k][w] = (double)v[k];
    __syncthreads();
    if (x == 0) {
#pragma unroll
        for (int k = 0; k < 6; k++)
            d_partial[bid][k] = sacc[k][0] + sacc[k][1] + sacc[k][2] + sacc[k][3];
        __threadfence();
        unsigned old = atomicInc(&d_ticket, GRID_ - 1);   // wraps -> self-reset
        s_last = (old == GRID_ - 1);
    }
    __syncthreads();

    // ---- last block: deterministic final combine ----
    if (s_last) {
        __threadfence();
        int t = x;
        double tot = 0.0;
        for (int bb = 0; bb < B_; bb++) {
            double u[6];
#pragma unroll
            for (int k = 0; k < 6; k++) u[k] = d_partial[bb * H_ + t][k];
#pragma unroll
            for (int off = 16; off; off >>= 1)
#pragma unroll
                for (int k = 0; k < 6; k++) u[k] += __shfl_down_sync(0xffffffffu, u[k], off);
            __syncthreads();
            if ((t & 31) == 0)
#pragma unroll
                for (int k = 0; k < 6; k++) sacc[k][t >> 5] = u[k];
            __syncthreads();
            if (t == 0) {
                double iouS  = sacc[0][0] + sacc[0][1] + sacc[0][2] + sacc[0][3];
                double slocS = sacc[1][0] + sacc[1][1] + sacc[1][2] + sacc[1][3];
                double gravS = sacc[2][0] + sacc[2][1] + sacc[2][2] + sacc[2][3];
                double hposS = sacc[3][0] + sacc[3][1] + sacc[3][2] + sacc[3][3];
                double hnegS = sacc[4][0] + sacc[4][1] + sacc[4][2] + sacc[4][3];
                double shgS  = sacc[5][0] + sacc[5][1] + sacc[5][2] + sacc[5][3];
                double HWC = (double)(H_ * W_ * C_);
                double hm_loss = hnegS / (HWC - shgS);
                bool cond = (shgS != 0.0);
                double hm2 = hm_loss + hposS / (cond ? shgS : 1.0);
                double safe_loc = (slocS > 0.0) ? slocS : 1.0;
                double iou_out = cond ? (iouS / safe_loc) : 0.0;
                double nvf = (d_nv[bb] > 1) ? (double)d_nv[bb] : 1.0;
                double grav_out = cond ? (gravS / nvf) : 0.0;
                tot += cond ? (iou_out + grav_out + hm2) : hm_loss;
            }
        }
        if (t == 0) out[0] = (float)(tot * (1.0 / B_));
    }
}

// ---------------- launch ----------------
extern "C" void kernel_launch(void* const* d_in, const int* in_sizes, int n_in,
                              void* d_out, int out_size) {
    const float* keypoints = (const float*)d_in[0];
    const float* preg      = (const float*)d_in[1];
    const float* fpn       = (const float*)d_in[2];
    const float* gt        = (const float*)d_in[3];
    const float* masks     = (const float*)d_in[4];
    const float* sy        = (const float*)d_in[5];
    const float* sx        = (const float*)d_in[6];
    (void)in_sizes; (void)n_in; (void)out_size;

    fused_kernel<<<GRID_, 128>>>(keypoints, preg, fpn, masks, gt, sy, sx, (float*)d_out);
}